// round 8
// baseline (speedup 1.0000x reference)
#include <cuda_runtime.h>
#include <cstdint>

// FineMatching: per match m (grid.x):
//   sims[l][s] = dot(x0[m,l,:], x1[m,s,:]) / 128   (64x64x128 GEMM, 3xTF32 mma.sync)
//   heatmap    = softmax_l(sims) * softmax_s(sims)
//   masked argmax -> idx_l, idx_s, biases
//
// d_out (f32): [ heatmap M*4096 | idx_l M | idx_s M | biases0 2M | biases1 2M ]
//
// Round-8: 256 threads (8 warps), warp w computes sims[0:64, w*8:(w+1)*8].
// A split hi/lo once at staging (ldmatrix.x4 fragments); B raw, split in regs.
// Epilogue in acc layout, no-max softmax. 2 CTAs/SM -> 16 warps/SM.

#define NTHREADS 256

// ---- smem byte offsets ----
#define OFF_AH 0                    // A hi plane, 64 x 512B, XOR-swizzled
#define OFF_AL 32768                // A lo plane
#define OFF_B  65536                // B raw f32, swizzled
#define OFF_RP 98304                // row partials: 64 x 8 f32
#define OFF_RI (OFF_RP + 2048)      // rinv 64 f32
#define OFF_CS (OFF_RI + 256)       // csum 64 f32
#define OFF_CI (OFF_CS + 256)       // cinv 64 f32
#define OFF_RV (OFF_CI + 256)       // 8 f32
#define OFF_RX (OFF_RV + 32)        // 8 i32
#define SMEM_BYTES (OFF_RX + 32)

__device__ __forceinline__ uint32_t smem_u32(const void* p) {
    uint32_t a;
    asm("{ .reg .u64 t; cvta.to.shared.u64 t, %1; cvt.u32.u64 %0, t; }" : "=r"(a) : "l"(p));
    return a;
}

__device__ __forceinline__ uint32_t f2tf32(float f) {
    uint32_t r;
    asm("cvt.rna.tf32.f32 %0, %1;" : "=r"(r) : "f"(f));
    return r;
}

__device__ __forceinline__ void split_tf32(float f, uint32_t& hi, uint32_t& lo) {
    hi = f2tf32(f);
    float r = f - __uint_as_float(hi);
    lo = f2tf32(r);
}

__device__ __forceinline__ void ldsm_x4(uint32_t& r0, uint32_t& r1, uint32_t& r2,
                                        uint32_t& r3, uint32_t addr) {
    asm volatile("ldmatrix.sync.aligned.m8n8.x4.shared.b16 {%0,%1,%2,%3}, [%4];"
                 : "=r"(r0), "=r"(r1), "=r"(r2), "=r"(r3) : "r"(addr));
}

__device__ __forceinline__ void mma_tf32(float& d0, float& d1, float& d2, float& d3,
                                         uint32_t a0, uint32_t a1, uint32_t a2, uint32_t a3,
                                         uint32_t b0, uint32_t b1) {
    asm volatile(
        "mma.sync.aligned.m16n8k8.row.col.f32.tf32.tf32.f32 "
        "{%0,%1,%2,%3}, {%4,%5,%6,%7}, {%8,%9}, {%0,%1,%2,%3};"
        : "+f"(d0), "+f"(d1), "+f"(d2), "+f"(d3)
        : "r"(a0), "r"(a1), "r"(a2), "r"(a3), "r"(b0), "r"(b1));
}

__device__ __forceinline__ bool inner_mask(int p) {
    int y = p >> 3, x = p & 7;
    return (y >= 1) & (y <= 6) & (x >= 1) & (x <= 6);
}

__global__ void __launch_bounds__(NTHREADS, 2)
fm_kernel(const float* __restrict__ x0, const float* __restrict__ x1,
          float* __restrict__ hm, float* __restrict__ oil,
          float* __restrict__ ois, float* __restrict__ ob0,
          float* __restrict__ ob1) {
    extern __shared__ char sm[];
    float* rowpart = (float*)(sm + OFF_RP);
    float* rinv_s  = (float*)(sm + OFF_RI);
    float* csum_s  = (float*)(sm + OFF_CS);
    float* cinv_s  = (float*)(sm + OFF_CI);
    float* redv    = (float*)(sm + OFF_RV);
    int*   redi    = (int*)(sm + OFF_RX);

    const int m    = blockIdx.x;
    const int tid  = threadIdx.x;
    const int warp = tid >> 5;
    const int lane = tid & 31;
    const int g    = lane >> 2;        // group 0..7
    const int tig  = lane & 3;         // thread-in-group

    // ---- stage: A split hi/lo into planes; B raw. XOR-chunk swizzled ----
    {
        const float4* p0 = (const float4*)(x0 + (size_t)m * 8192);
        const float4* p1 = (const float4*)(x1 + (size_t)m * 8192);
        uint4*  ahv = (uint4*)(sm + OFF_AH);
        uint4*  alv = (uint4*)(sm + OFF_AL);
        float4* bv  = (float4*)(sm + OFF_B);
#pragma unroll
        for (int it = 0; it < 8; it++) {
            int i = tid + it * NTHREADS;       // float4 idx 0..2047
            int row = i >> 5;
            int ch  = i & 31;
            int pch = ch ^ (row & 7);
            float4 a4 = p0[i];
            float4 b4 = p1[i];
            uint4 hi4, lo4;
            split_tf32(a4.x, hi4.x, lo4.x);
            split_tf32(a4.y, hi4.y, lo4.y);
            split_tf32(a4.z, hi4.z, lo4.z);
            split_tf32(a4.w, hi4.w, lo4.w);
            ahv[row * 32 + pch] = hi4;
            alv[row * 32 + pch] = lo4;
            bv[row * 32 + pch]  = b4;
        }
    }
    __syncthreads();

    // ---- GEMM: warp w -> sims[0:64, w*8:(w+1)*8], 3xTF32 ----
    float acc[4][4];
#pragma unroll
    for (int mt = 0; mt < 4; mt++)
#pragma unroll
        for (int qq = 0; qq < 4; qq++) acc[mt][qq] = 0.0f;

    const uint32_t smb = smem_u32(sm);

    // ldmatrix lane addressing for A
    const int qm = lane >> 3;           // matrix id 0..3
    const int rm = lane & 7;            // row within matrix
    const uint32_t kq = (uint32_t)((qm >> 1) << 4);
    uint32_t abase[4], axm[4];
#pragma unroll
    for (int mt = 0; mt < 4; mt++) {
        int row = mt * 16 + ((qm & 1) << 3) + rm;
        abase[mt] = smb + OFF_AH + row * 512;
        axm[mt]   = (uint32_t)((row & 7) << 4);
    }
    // B addressing (scalar LDS per fragment): s-row = warp*8 + g
    const uint32_t bbase = OFF_B + (warp * 8 + g) * 512 + tig * 4;
    const uint32_t bswz  = (uint32_t)(((warp * 8 + g) & 7) << 4);

#pragma unroll 4
    for (int kt = 0; kt < 16; kt++) {
        uint32_t c0 = (uint32_t)(kt << 5);
        uint32_t c1 = c0 + 16;
        uint32_t koff = c0 | kq;
        // B fragment: raw f32 loads, split in registers
        uint32_t bh0, bl0, bh1, bl1;
        {
            float f0 = *(const float*)(sm + bbase + (c0 ^ bswz));
            float f1 = *(const float*)(sm + bbase + (c1 ^ bswz));
            split_tf32(f0, bh0, bl0);
            split_tf32(f1, bh1, bl1);
        }
#pragma unroll
        for (int mt = 0; mt < 4; mt++) {
            uint32_t ad = abase[mt] + (koff ^ axm[mt]);
            uint32_t ah0, ah1, ah2, ah3, al0, al1, al2, al3;
            ldsm_x4(ah0, ah1, ah2, ah3, ad);
            ldsm_x4(al0, al1, al2, al3, ad + 32768);
            float* d = acc[mt];
            mma_tf32(d[0], d[1], d[2], d[3], al0, al1, al2, al3, bh0, bh1);
            mma_tf32(d[0], d[1], d[2], d[3], ah0, ah1, ah2, ah3, bl0, bl1);
            mma_tf32(d[0], d[1], d[2], d[3], ah0, ah1, ah2, ah3, bh0, bh1);
        }
    }

    // ---- epilogue in accumulator layout ----
    // acc[mt][0]: (row=mt*16+g,   col=warp*8+2tig)
    // acc[mt][1]: (row,           col+1)
    // acc[mt][2]: (row+8,         col)
    // acc[mt][3]: (row+8,         col+1)
    const float inv128 = 1.0f / 128.0f;
#pragma unroll
    for (int mt = 0; mt < 4; mt++)
#pragma unroll
        for (int qq = 0; qq < 4; qq++)
            acc[mt][qq] = __expf(acc[mt][qq] * inv128);

    // row partial sums (this warp's 8 cols) -> rowpart[row*8 + warp]
#pragma unroll
    for (int mt = 0; mt < 4; mt++) {
        float r0 = acc[mt][0] + acc[mt][1];
        float r1 = acc[mt][2] + acc[mt][3];
        r0 += __shfl_xor_sync(0xffffffffu, r0, 1);
        r0 += __shfl_xor_sync(0xffffffffu, r0, 2);
        r1 += __shfl_xor_sync(0xffffffffu, r1, 1);
        r1 += __shfl_xor_sync(0xffffffffu, r1, 2);
        if (tig == 0) {
            rowpart[(mt * 16 + g) * 8 + warp]     = r0;
            rowpart[(mt * 16 + g + 8) * 8 + warp] = r1;
        }
    }
    // col sums (warp-exclusive cols): reduce over g via shuffles
    {
        float c0 = acc[0][0] + acc[0][2];
        float c1 = acc[0][1] + acc[0][3];
#pragma unroll
        for (int mt = 1; mt < 4; mt++) {
            c0 += acc[mt][0] + acc[mt][2];
            c1 += acc[mt][1] + acc[mt][3];
        }
        c0 += __shfl_xor_sync(0xffffffffu, c0, 4);
        c0 += __shfl_xor_sync(0xffffffffu, c0, 8);
        c0 += __shfl_xor_sync(0xffffffffu, c0, 16);
        c1 += __shfl_xor_sync(0xffffffffu, c1, 4);
        c1 += __shfl_xor_sync(0xffffffffu, c1, 8);
        c1 += __shfl_xor_sync(0xffffffffu, c1, 16);
        if (g == 0)
            *(float2*)(csum_s + warp * 8 + 2 * tig) = make_float2(c0, c1);
    }
    __syncthreads();
    if (tid < 64) {
        const float4* rp = (const float4*)(rowpart + tid * 8);
        float4 p0 = rp[0], p1 = rp[1];
        rinv_s[tid] = 1.0f / (((p0.x + p0.y) + (p0.z + p0.w)) +
                              ((p1.x + p1.y) + (p1.z + p1.w)));
    } else if (tid < 128) {
        int c = tid - 64;
        cinv_s[c] = 1.0f / csum_s[c];
    }
    __syncthreads();

    // h-pass: h = e*e*rinv[row]*cinv[col]; store + masked argmax
    float rin[4][2];
#pragma unroll
    for (int mt = 0; mt < 4; mt++) {
        rin[mt][0] = rinv_s[mt * 16 + g];
        rin[mt][1] = rinv_s[mt * 16 + g + 8];
    }
    const int col0 = warp * 8 + 2 * tig;
    float2 cin = *(const float2*)(cinv_s + col0);
    bool mc0 = inner_mask(col0), mc1 = inner_mask(col0 + 1);

    float bestv = -1.0f;
    int   besti = 0;
    float* hmbase = hm + (size_t)m * 4096;
#pragma unroll
    for (int mt = 0; mt < 4; mt++) {
        int row0 = mt * 16 + g;
        float h0 = acc[mt][0] * acc[mt][0] * rin[mt][0] * cin.x;
        float h1 = acc[mt][1] * acc[mt][1] * rin[mt][0] * cin.y;
        float h2 = acc[mt][2] * acc[mt][2] * rin[mt][1] * cin.x;
        float h3 = acc[mt][3] * acc[mt][3] * rin[mt][1] * cin.y;
        *(float2*)(hmbase + row0 * 64 + col0)       = make_float2(h0, h1);
        *(float2*)(hmbase + (row0 + 8) * 64 + col0) = make_float2(h2, h3);
        if (inner_mask(row0)) {
            if (mc0) {
                int fi = (row0 << 6) | col0;
                if (h0 > bestv || (h0 == bestv && fi < besti)) { bestv = h0; besti = fi; }
            }
            if (mc1) {
                int fi = (row0 << 6) | (col0 + 1);
                if (h1 > bestv || (h1 == bestv && fi < besti)) { bestv = h1; besti = fi; }
            }
        }
        if (inner_mask(row0 + 8)) {
            if (mc0) {
                int fi = ((row0 + 8) << 6) | col0;
                if (h2 > bestv || (h2 == bestv && fi < besti)) { bestv = h2; besti = fi; }
            }
            if (mc1) {
                int fi = ((row0 + 8) << 6) | (col0 + 1);
                if (h3 > bestv || (h3 == bestv && fi < besti)) { bestv = h3; besti = fi; }
            }
        }
    }

    // warp argmax reduce (min flat idx on ties)
#pragma unroll
    for (int off = 16; off >= 1; off >>= 1) {
        float ov = __shfl_xor_sync(0xffffffffu, bestv, off);
        int   oi = __shfl_xor_sync(0xffffffffu, besti, off);
        if (ov > bestv || (ov == bestv && oi < besti)) { bestv = ov; besti = oi; }
    }
    if (lane == 0) { redv[warp] = bestv; redi[warp] = besti; }
    __syncthreads();
    if (tid == 0) {
        float bv = redv[0];
        int   bx = redi[0];
#pragma unroll
        for (int w = 1; w < 8; w++) {
            float ov = redv[w];
            int   oi = redi[w];
            if (ov > bv || (ov == bv && oi < bx)) { bv = ov; bx = oi; }
        }
        int il = bx >> 6;
        int is = bx & 63;
        oil[m] = (float)il;
        ois[m] = (float)is;
        ob0[2 * m + 0] = (float)(il & 7) - 3.5f;
        ob0[2 * m + 1] = (float)(il >> 3) - 3.5f;
        ob1[2 * m + 0] = (float)(is & 7) - 3.5f;
        ob1[2 * m + 1] = (float)(is >> 3) - 3.5f;
    }
}

extern "C" void kernel_launch(void* const* d_in, const int* in_sizes, int n_in,
                              void* d_out, int out_size) {
    const float* x0 = (const float*)d_in[0];
    const float* x1 = (const float*)d_in[1];
    const int M = in_sizes[0] / (64 * 128);

    float* out = (float*)d_out;
    float* hm  = out;
    float* oil = hm + (size_t)M * 4096;
    float* ois = oil + M;
    float* ob0 = ois + M;
    float* ob1 = ob0 + 2 * (size_t)M;

    cudaFuncSetAttribute(fm_kernel, cudaFuncAttributeMaxDynamicSharedMemorySize,
                         SMEM_BYTES);
    fm_kernel<<<M, NTHREADS, SMEM_BYTES>>>(x0, x1, hm, oil, ois, ob0, ob1);
}

// round 9
// speedup vs baseline: 1.1051x; 1.1051x over previous
#include <cuda_runtime.h>
#include <cstdint>

// FineMatching: per match m (grid.x):
//   sims[l][s] = dot(x0[m,l,:], x1[m,s,:]) / 128   (64x64x128 GEMM, 3xTF32 mma.sync)
//   heatmap    = softmax_l(sims) * softmax_s(sims)
//   masked argmax -> idx_l, idx_s, biases
//
// d_out (f32): [ heatmap M*4096 | idx_l M | idx_s M | biases0 2M | biases1 2M ]
//
// Round-9: 256 threads, 8 warps in 2x4 (rowhalf x colquarter) grid; each warp
// computes 32x16. ldsm traffic same as round-7 (A reuse over nt preserved),
// warps/SM doubled. A split hi/lo at staging; B raw, split in regs.

#define NTHREADS 256

// ---- smem byte offsets ----
#define OFF_AH 0                    // A hi plane, 64 x 512B, XOR-swizzled
#define OFF_AL 32768                // A lo plane
#define OFF_B  65536                // B raw f32, swizzled
#define OFF_RP 98304                // row partials: 64 x 4 f32
#define OFF_CP (OFF_RP + 1024)      // col partials: 2 x 64 f32
#define OFF_RI (OFF_CP + 512)       // rinv 64 f32
#define OFF_CI (OFF_RI + 256)       // cinv 64 f32
#define OFF_RV (OFF_CI + 256)       // 8 f32
#define OFF_RX (OFF_RV + 32)        // 8 i32
#define SMEM_BYTES (OFF_RX + 32)

__device__ __forceinline__ uint32_t smem_u32(const void* p) {
    uint32_t a;
    asm("{ .reg .u64 t; cvta.to.shared.u64 t, %1; cvt.u32.u64 %0, t; }" : "=r"(a) : "l"(p));
    return a;
}

__device__ __forceinline__ uint32_t f2tf32(float f) {
    uint32_t r;
    asm("cvt.rna.tf32.f32 %0, %1;" : "=r"(r) : "f"(f));
    return r;
}

__device__ __forceinline__ void split_tf32(float f, uint32_t& hi, uint32_t& lo) {
    hi = f2tf32(f);
    float r = f - __uint_as_float(hi);
    lo = f2tf32(r);
}

__device__ __forceinline__ void ldsm_x4(uint32_t& r0, uint32_t& r1, uint32_t& r2,
                                        uint32_t& r3, uint32_t addr) {
    asm volatile("ldmatrix.sync.aligned.m8n8.x4.shared.b16 {%0,%1,%2,%3}, [%4];"
                 : "=r"(r0), "=r"(r1), "=r"(r2), "=r"(r3) : "r"(addr));
}

__device__ __forceinline__ void mma_tf32(float& d0, float& d1, float& d2, float& d3,
                                         uint32_t a0, uint32_t a1, uint32_t a2, uint32_t a3,
                                         uint32_t b0, uint32_t b1) {
    asm volatile(
        "mma.sync.aligned.m16n8k8.row.col.f32.tf32.tf32.f32 "
        "{%0,%1,%2,%3}, {%4,%5,%6,%7}, {%8,%9}, {%0,%1,%2,%3};"
        : "+f"(d0), "+f"(d1), "+f"(d2), "+f"(d3)
        : "r"(a0), "r"(a1), "r"(a2), "r"(a3), "r"(b0), "r"(b1));
}

__device__ __forceinline__ bool inner_mask(int p) {
    int y = p >> 3, x = p & 7;
    return (y >= 1) & (y <= 6) & (x >= 1) & (x <= 6);
}

__global__ void __launch_bounds__(NTHREADS, 2)
fm_kernel(const float* __restrict__ x0, const float* __restrict__ x1,
          float* __restrict__ hm, float* __restrict__ oil,
          float* __restrict__ ois, float* __restrict__ ob0,
          float* __restrict__ ob1) {
    extern __shared__ char sm[];
    float* rowpart = (float*)(sm + OFF_RP);
    float* colpart = (float*)(sm + OFF_CP);
    float* rinv_s  = (float*)(sm + OFF_RI);
    float* cinv_s  = (float*)(sm + OFF_CI);
    float* redv    = (float*)(sm + OFF_RV);
    int*   redi    = (int*)(sm + OFF_RX);

    const int m    = blockIdx.x;
    const int tid  = threadIdx.x;
    const int warp = tid >> 5;
    const int lane = tid & 31;
    const int g    = lane >> 2;
    const int tig  = lane & 3;
    const int wc   = warp & 3;          // col quarter (16 cols)
    const int wr   = warp >> 2;         // row half (32 rows)

    // ---- stage: A split hi/lo; B raw. XOR-chunk swizzled ----
    {
        const float4* p0 = (const float4*)(x0 + (size_t)m * 8192);
        const float4* p1 = (const float4*)(x1 + (size_t)m * 8192);
        uint4*  ahv = (uint4*)(sm + OFF_AH);
        uint4*  alv = (uint4*)(sm + OFF_AL);
        float4* bv  = (float4*)(sm + OFF_B);
#pragma unroll
        for (int it = 0; it < 8; it++) {
            int i = tid + it * NTHREADS;
            int row = i >> 5;
            int ch  = i & 31;
            int pch = ch ^ (row & 7);
            float4 a4 = p0[i];
            float4 b4 = p1[i];
            uint4 hi4, lo4;
            split_tf32(a4.x, hi4.x, lo4.x);
            split_tf32(a4.y, hi4.y, lo4.y);
            split_tf32(a4.z, hi4.z, lo4.z);
            split_tf32(a4.w, hi4.w, lo4.w);
            ahv[row * 32 + pch] = hi4;
            alv[row * 32 + pch] = lo4;
            bv[row * 32 + pch]  = b4;
        }
    }
    __syncthreads();

    // ---- GEMM: warp (wr,wc) -> sims[wr*32:+32, wc*16:+16], 3xTF32 ----
    float acc[2][2][4];
#pragma unroll
    for (int mt = 0; mt < 2; mt++)
#pragma unroll
        for (int nt = 0; nt < 2; nt++)
#pragma unroll
            for (int qq = 0; qq < 4; qq++) acc[mt][nt][qq] = 0.0f;

    const uint32_t smb = smem_u32(sm);

    const int qm = lane >> 3;
    const int rm = lane & 7;
    const uint32_t kq = (uint32_t)((qm >> 1) << 4);
    uint32_t abase[2], axm[2];
#pragma unroll
    for (int mt = 0; mt < 2; mt++) {
        int row = wr * 32 + mt * 16 + ((qm & 1) << 3) + rm;
        abase[mt] = smb + OFF_AH + row * 512;
        axm[mt]   = (uint32_t)((row & 7) << 4);
    }
    uint32_t bbase[2], bswz[2];
#pragma unroll
    for (int nt = 0; nt < 2; nt++) {
        int row = wc * 16 + nt * 8 + g;
        bbase[nt] = OFF_B + row * 512 + tig * 4;
        bswz[nt]  = (uint32_t)((row & 7) << 4);
    }

#pragma unroll 4
    for (int kt = 0; kt < 16; kt++) {
        uint32_t c0 = (uint32_t)(kt << 5);
        uint32_t c1 = c0 + 16;
        uint32_t koff = c0 | kq;
        uint32_t bh[2][2], bl[2][2];
#pragma unroll
        for (int nt = 0; nt < 2; nt++) {
            float f0 = *(const float*)(sm + bbase[nt] + (c0 ^ bswz[nt]));
            float f1 = *(const float*)(sm + bbase[nt] + (c1 ^ bswz[nt]));
            split_tf32(f0, bh[nt][0], bl[nt][0]);
            split_tf32(f1, bh[nt][1], bl[nt][1]);
        }
#pragma unroll
        for (int mt = 0; mt < 2; mt++) {
            uint32_t ad = abase[mt] + (koff ^ axm[mt]);
            uint32_t ah0, ah1, ah2, ah3, al0, al1, al2, al3;
            ldsm_x4(ah0, ah1, ah2, ah3, ad);
            ldsm_x4(al0, al1, al2, al3, ad + 32768);
#pragma unroll
            for (int nt = 0; nt < 2; nt++) {
                float* d = acc[mt][nt];
                mma_tf32(d[0], d[1], d[2], d[3], al0, al1, al2, al3, bh[nt][0], bh[nt][1]);
                mma_tf32(d[0], d[1], d[2], d[3], ah0, ah1, ah2, ah3, bl[nt][0], bl[nt][1]);
                mma_tf32(d[0], d[1], d[2], d[3], ah0, ah1, ah2, ah3, bh[nt][0], bh[nt][1]);
            }
        }
    }

    // ---- epilogue in acc layout ----
    // acc[mt][nt][0]: (row = wr*32+mt*16+g, col = wc*16+nt*8+2tig); [1]: col+1;
    // [2]: row+8; [3]: row+8,col+1
    const float inv128 = 1.0f / 128.0f;
#pragma unroll
    for (int mt = 0; mt < 2; mt++)
#pragma unroll
        for (int nt = 0; nt < 2; nt++)
#pragma unroll
            for (int qq = 0; qq < 4; qq++)
                acc[mt][nt][qq] = __expf(acc[mt][nt][qq] * inv128);

    // row partial sums (warp's 16 cols) -> rowpart[row*4 + wc]
#pragma unroll
    for (int mt = 0; mt < 2; mt++) {
        float r0 = acc[mt][0][0] + acc[mt][0][1] + acc[mt][1][0] + acc[mt][1][1];
        float r1 = acc[mt][0][2] + acc[mt][0][3] + acc[mt][1][2] + acc[mt][1][3];
        r0 += __shfl_xor_sync(0xffffffffu, r0, 1);
        r0 += __shfl_xor_sync(0xffffffffu, r0, 2);
        r1 += __shfl_xor_sync(0xffffffffu, r1, 1);
        r1 += __shfl_xor_sync(0xffffffffu, r1, 2);
        if (tig == 0) {
            int row = wr * 32 + mt * 16 + g;
            rowpart[row * 4 + wc]       = r0;
            rowpart[(row + 8) * 4 + wc] = r1;
        }
    }
    // col partial sums (warp's 32 rows) -> colpart[wr*64 + col]
#pragma unroll
    for (int nt = 0; nt < 2; nt++) {
        float c0 = acc[0][nt][0] + acc[0][nt][2] + acc[1][nt][0] + acc[1][nt][2];
        float c1 = acc[0][nt][1] + acc[0][nt][3] + acc[1][nt][1] + acc[1][nt][3];
        c0 += __shfl_xor_sync(0xffffffffu, c0, 4);
        c0 += __shfl_xor_sync(0xffffffffu, c0, 8);
        c0 += __shfl_xor_sync(0xffffffffu, c0, 16);
        c1 += __shfl_xor_sync(0xffffffffu, c1, 4);
        c1 += __shfl_xor_sync(0xffffffffu, c1, 8);
        c1 += __shfl_xor_sync(0xffffffffu, c1, 16);
        if (g == 0)
            *(float2*)(colpart + wr * 64 + wc * 16 + nt * 8 + 2 * tig) =
                make_float2(c0, c1);
    }
    __syncthreads();
    if (tid < 64) {
        const float4* rp = (const float4*)(rowpart + tid * 4);
        float4 p = rp[0];
        rinv_s[tid] = 1.0f / ((p.x + p.y) + (p.z + p.w));
    } else if (tid < 128) {
        int c = tid - 64;
        cinv_s[c] = 1.0f / (colpart[c] + colpart[64 + c]);
    }
    __syncthreads();

    // h-pass: h = e*e*rinv[row]*cinv[col]; store + masked argmax
    float rin[2][2];
#pragma unroll
    for (int mt = 0; mt < 2; mt++) {
        rin[mt][0] = rinv_s[wr * 32 + mt * 16 + g];
        rin[mt][1] = rinv_s[wr * 32 + mt * 16 + g + 8];
    }
    float2 cin[2];
    bool mcol[2][2];
#pragma unroll
    for (int nt = 0; nt < 2; nt++) {
        int c = wc * 16 + nt * 8 + 2 * tig;
        cin[nt] = *(const float2*)(cinv_s + c);
        mcol[nt][0] = inner_mask(c);
        mcol[nt][1] = inner_mask(c + 1);
    }

    float bestv = -1.0f;
    int   besti = 0;
    float* hmbase = hm + (size_t)m * 4096;
#pragma unroll
    for (int mt = 0; mt < 2; mt++) {
        int row0 = wr * 32 + mt * 16 + g;
        bool mr0 = inner_mask(row0);
        bool mr1 = inner_mask(row0 + 8);
#pragma unroll
        for (int nt = 0; nt < 2; nt++) {
            int col0 = wc * 16 + nt * 8 + 2 * tig;
            float h0 = acc[mt][nt][0] * acc[mt][nt][0] * rin[mt][0] * cin[nt].x;
            float h1 = acc[mt][nt][1] * acc[mt][nt][1] * rin[mt][0] * cin[nt].y;
            float h2 = acc[mt][nt][2] * acc[mt][nt][2] * rin[mt][1] * cin[nt].x;
            float h3 = acc[mt][nt][3] * acc[mt][nt][3] * rin[mt][1] * cin[nt].y;
            *(float2*)(hmbase + row0 * 64 + col0)       = make_float2(h0, h1);
            *(float2*)(hmbase + (row0 + 8) * 64 + col0) = make_float2(h2, h3);
            if (mr0) {
                if (mcol[nt][0]) {
                    int fi = (row0 << 6) | col0;
                    if (h0 > bestv || (h0 == bestv && fi < besti)) { bestv = h0; besti = fi; }
                }
                if (mcol[nt][1]) {
                    int fi = (row0 << 6) | (col0 + 1);
                    if (h1 > bestv || (h1 == bestv && fi < besti)) { bestv = h1; besti = fi; }
                }
            }
            if (mr1) {
                if (mcol[nt][0]) {
                    int fi = ((row0 + 8) << 6) | col0;
                    if (h2 > bestv || (h2 == bestv && fi < besti)) { bestv = h2; besti = fi; }
                }
                if (mcol[nt][1]) {
                    int fi = ((row0 + 8) << 6) | (col0 + 1);
                    if (h3 > bestv || (h3 == bestv && fi < besti)) { bestv = h3; besti = fi; }
                }
            }
        }
    }

    // warp argmax reduce (min flat idx on ties)
#pragma unroll
    for (int off = 16; off >= 1; off >>= 1) {
        float ov = __shfl_xor_sync(0xffffffffu, bestv, off);
        int   oi = __shfl_xor_sync(0xffffffffu, besti, off);
        if (ov > bestv || (ov == bestv && oi < besti)) { bestv = ov; besti = oi; }
    }
    if (lane == 0) { redv[warp] = bestv; redi[warp] = besti; }
    __syncthreads();
    if (tid == 0) {
        float bv = redv[0];
        int   bx = redi[0];
#pragma unroll
        for (int w = 1; w < 8; w++) {
            float ov = redv[w];
            int   oi = redi[w];
            if (ov > bv || (ov == bv && oi < bx)) { bv = ov; bx = oi; }
        }
        int il = bx >> 6;
        int is = bx & 63;
        oil[m] = (float)il;
        ois[m] = (float)is;
        ob0[2 * m + 0] = (float)(il & 7) - 3.5f;
        ob0[2 * m + 1] = (float)(il >> 3) - 3.5f;
        ob1[2 * m + 0] = (float)(is & 7) - 3.5f;
        ob1[2 * m + 1] = (float)(is >> 3) - 3.5f;
    }
}

extern "C" void kernel_launch(void* const* d_in, const int* in_sizes, int n_in,
                              void* d_out, int out_size) {
    const float* x0 = (const float*)d_in[0];
    const float* x1 = (const float*)d_in[1];
    const int M = in_sizes[0] / (64 * 128);

    float* out = (float*)d_out;
    float* hm  = out;
    float* oil = hm + (size_t)M * 4096;
    float* ois = oil + M;
    float* ob0 = ois + M;
    float* ob1 = ob0 + 2 * (size_t)M;

    cudaFuncSetAttribute(fm_kernel, cudaFuncAttributeMaxDynamicSharedMemorySize,
                         SMEM_BYTES);
    fm_kernel<<<M, NTHREADS, SMEM_BYTES>>>(x0, x1, hm, oil, ois, ob0, ob1);
}